// round 6
// baseline (speedup 1.0000x reference)
#include <cuda_runtime.h>
#include <cstdint>

// Problem shape (dataset-fixed, sizes read dynamically):
//   child_val:    (1, 2,000,000) float32   -> d_in[0]   (8MB, L2-resident)
//   flat_indices: (32,000,000,)  int32     -> d_in[1]
//   segment_ids:  (32,000,000,)  int32 sorted -> d_in[2]
//   out:          (1, 1,000,000) float32
//
// Bottleneck (R1-R5 ncu): L1tex wavefront pipe (88.4%) + L2 sector rate
// (~95% of LTS cap) on 32M divergent gathers. R5 = 123.4us vs ~110-115us
// floor. This round: persistent grid-stride kernel (one wave instead of
// 13.2) to remove wave-transition overhead and straggler spread.

static constexpr int EPT = 8;            // edges per thread per iteration
static constexpr int TPB = 256;          // threads per block
static constexpr int BPSM = 8;           // blocks per SM (regs=32 fits)
static constexpr unsigned FULL = 0xFFFFFFFFu;

__global__ void zero_out_kernel(float4* __restrict__ out, int n4) {
    int i = blockIdx.x * blockDim.x + threadIdx.x;
    if (i < n4) out[i] = make_float4(0.f, 0.f, 0.f, 0.f);
}

__global__ __launch_bounds__(TPB, BPSM) void segsum_kernel(
    const float* __restrict__ cv,
    const int*   __restrict__ fi,
    const int*   __restrict__ seg,
    float*       __restrict__ out,
    long long E)
{
    const int lane = threadIdx.x & 31;
    const long long warps_total = ((long long)gridDim.x * TPB) >> 5;
    const long long chunk_sz    = 32LL * EPT;                 // 256 edges/warp/iter
    long long warp_gid = ((long long)blockIdx.x * TPB + threadIdx.x) >> 5;

    for (long long warp_base = warp_gid * chunk_sz;
         warp_base < E;
         warp_base += warps_total * chunk_sz)
    {
        if (warp_base + chunk_sz <= E) {
            // ---- Full-warp fast path ----
            long long base = warp_base + (long long)lane * EPT;

            int4  i4[EPT / 4];
            int4  s4[EPT / 4];
            float v [EPT];

            // seg vectors first (independent; in flight under gather chain).
            // .cs: read-once streams, evict-first -> keep L2 for the table.
            #pragma unroll
            for (int k = 0; k < EPT / 4; k++)
                s4[k] = __ldcs(reinterpret_cast<const int4*>(seg + base + 4 * k));

            #pragma unroll
            for (int k = 0; k < EPT / 4; k++)
                i4[k] = __ldcs(reinterpret_cast<const int4*>(fi + base + 4 * k));

            // Gathers: L2-only (.cg) — 8MB table, ~97% L1 miss.
            #pragma unroll
            for (int k = 0; k < EPT / 4; k++) {
                v[4 * k + 0] = __ldcg(cv + i4[k].x);
                v[4 * k + 1] = __ldcg(cv + i4[k].y);
                v[4 * k + 2] = __ldcg(cv + i4[k].z);
                v[4 * k + 3] = __ldcg(cv + i4[k].w);
            }

            int se[EPT];
            #pragma unroll
            for (int k = 0; k < EPT / 4; k++) {
                se[4 * k + 0] = s4[k].x; se[4 * k + 1] = s4[k].y;
                se[4 * k + 2] = s4[k].z; se[4 * k + 3] = s4[k].w;
            }

            // Per-thread run-length pass: head run, interior atomics, tail.
            int   hs = se[0];  float ha = 0.f;
            bool  multi = false;
            int   cur = se[0]; float acc = v[0];
            #pragma unroll
            for (int e = 1; e < EPT; e++) {
                if (se[e] != cur) {
                    if (!multi) { hs = cur; ha = acc; multi = true; }
                    else        { atomicAdd(out + cur, acc); }
                    cur = se[e];
                    acc = v[e];
                } else {
                    acc += v[e];
                }
            }
            const int   ts = cur;
            const float ta = acc;

            // ---- Warp merge ----
            const int myhead = multi ? hs : ts;
            const int ts_prev = __shfl_up_sync(FULL, ts, 1);
            const bool conn = (lane > 0) && (myhead == ts_prev);

            // Segmented inclusive scan over tail partials.
            float c = ta;
            int   hflag = !(conn && !multi);
            #pragma unroll
            for (int d = 1; d < 32; d <<= 1) {
                float c_up = __shfl_up_sync(FULL, c, d);
                int   h_up = __shfl_up_sync(FULL, hflag, d);
                if (lane >= d) {
                    if (!hflag) c += c_up;
                    hflag |= h_up;
                }
            }

            const float cprev    = __shfl_up_sync(FULL, c, 1);
            const int   conn_nxt = __shfl_down_sync(FULL, (int)conn, 1);

            if (multi)
                atomicAdd(out + hs, conn ? (ha + cprev) : ha);

            if (lane == 31 || !conn_nxt)
                atomicAdd(out + ts, c);
        } else {
            // ---- Tail chunk: per-lane scalar, bounds-checked ----
            long long base = warp_base + (long long)lane * EPT;
            if (base < E) {
                long long end = base + EPT < E ? base + EPT : E;
                int   cur = -1;
                float acc = 0.f;
                for (long long e = base; e < end; e++) {
                    int s = seg[e];
                    float val = __ldcg(cv + fi[e]);
                    if (s != cur) {
                        if (cur >= 0) atomicAdd(out + cur, acc);
                        cur = s;
                        acc = val;
                    } else {
                        acc += val;
                    }
                }
                if (cur >= 0) atomicAdd(out + cur, acc);
            }
        }
    }
}

extern "C" void kernel_launch(void* const* d_in, const int* in_sizes, int n_in,
                              void* d_out, int out_size) {
    const float* cv  = (const float*)d_in[0];
    const int*   fi  = (const int*)d_in[1];
    const int*   seg = (const int*)d_in[2];
    float*       out = (float*)d_out;

    long long E = (long long)in_sizes[1];
    int N = out_size;

    // Zero output (harness poisons to 0xAA; empty segments must read 0).
    {
        int n4 = N / 4;
        int blocks = (n4 + TPB - 1) / TPB;
        zero_out_kernel<<<blocks, TPB>>>((float4*)out, n4);
    }

    int sm_count = 148;
    cudaDeviceGetAttribute(&sm_count, cudaDevAttrMultiProcessorCount, 0);
    int blocks = sm_count * BPSM;   // one persistent wave

    segsum_kernel<<<blocks, TPB>>>(cv, fi, seg, out, E);
}

// round 7
// speedup vs baseline: 1.0310x; 1.0310x over previous
#include <cuda_runtime.h>
#include <cstdint>

// Problem shape (dataset-fixed, sizes read dynamically):
//   child_val:    (1, 2,000,000) float32   -> d_in[0]   (8MB, L2-resident)
//   flat_indices: (32,000,000,)  int32     -> d_in[1]
//   segment_ids:  (32,000,000,)  int32 sorted -> d_in[2]
//   out:          (1, 1,000,000) float32
//
// Bottleneck (R1-R6 ncu): L1tex wavefront pipe (~88%) + L2 sector rate
// (~95% of LTS cap) on 32M divergent gathers. R6 persistent grid REGRESSED
// (static partition imbalance) -> back to oversubscribed multi-wave grid
// (HW work-stealing), keeping R6's .cs stream hints (read-once, evict-first
// -> preserve L2 residency of the 8MB gather table).

static constexpr int EPT = 8;            // edges per thread
static constexpr int TPB = 256;          // threads per block
static constexpr unsigned FULL = 0xFFFFFFFFu;

__global__ void zero_out_kernel(float4* __restrict__ out, int n4) {
    int i = blockIdx.x * blockDim.x + threadIdx.x;
    if (i < n4) out[i] = make_float4(0.f, 0.f, 0.f, 0.f);
}

__global__ __launch_bounds__(TPB, 8) void segsum_kernel(
    const float* __restrict__ cv,
    const int*   __restrict__ fi,
    const int*   __restrict__ seg,
    float*       __restrict__ out,
    long long E)
{
    const int lane = threadIdx.x & 31;
    long long warp_gid  = ((long long)blockIdx.x * TPB + threadIdx.x) >> 5;
    long long warp_base = warp_gid * 32 * EPT;
    if (warp_base >= E) return;

    if (warp_base + 32 * EPT <= E) {
        // ---- Full-warp fast path ----
        long long base = warp_base + (long long)lane * EPT;

        int4  i4[EPT / 4];
        int4  s4[EPT / 4];
        float v [EPT];

        // seg vectors first (independent; in flight under the gather chain).
        // .cs: read-once streams, evict-first -> keep L2 ways for the table.
        #pragma unroll
        for (int k = 0; k < EPT / 4; k++)
            s4[k] = __ldcs(reinterpret_cast<const int4*>(seg + base + 4 * k));

        #pragma unroll
        for (int k = 0; k < EPT / 4; k++)
            i4[k] = __ldcs(reinterpret_cast<const int4*>(fi + base + 4 * k));

        // Gathers: L2-only (.cg) — 8MB table, ~97% L1 miss.
        #pragma unroll
        for (int k = 0; k < EPT / 4; k++) {
            v[4 * k + 0] = __ldcg(cv + i4[k].x);
            v[4 * k + 1] = __ldcg(cv + i4[k].y);
            v[4 * k + 2] = __ldcg(cv + i4[k].z);
            v[4 * k + 3] = __ldcg(cv + i4[k].w);
        }

        int se[EPT];
        #pragma unroll
        for (int k = 0; k < EPT / 4; k++) {
            se[4 * k + 0] = s4[k].x; se[4 * k + 1] = s4[k].y;
            se[4 * k + 2] = s4[k].z; se[4 * k + 3] = s4[k].w;
        }

        // Per-thread run-length pass: head run, interior atomics, tail run.
        int   hs = se[0];  float ha = 0.f;
        bool  multi = false;
        int   cur = se[0]; float acc = v[0];
        #pragma unroll
        for (int e = 1; e < EPT; e++) {
            if (se[e] != cur) {
                if (!multi) { hs = cur; ha = acc; multi = true; }
                else        { atomicAdd(out + cur, acc); }   // interior (rare)
                cur = se[e];
                acc = v[e];
            } else {
                acc += v[e];
            }
        }
        const int   ts = cur;
        const float ta = acc;

        // ---- Warp merge ----
        const int myhead = multi ? hs : ts;
        const int ts_prev = __shfl_up_sync(FULL, ts, 1);
        const bool conn = (lane > 0) && (myhead == ts_prev);

        // Segmented inclusive scan over tail partials.
        float c = ta;
        int   hflag = !(conn && !multi);
        #pragma unroll
        for (int d = 1; d < 32; d <<= 1) {
            float c_up = __shfl_up_sync(FULL, c, d);
            int   h_up = __shfl_up_sync(FULL, hflag, d);
            if (lane >= d) {
                if (!hflag) c += c_up;
                hflag |= h_up;
            }
        }

        const float cprev    = __shfl_up_sync(FULL, c, 1);
        const int   conn_nxt = __shfl_down_sync(FULL, (int)conn, 1);

        if (multi)
            atomicAdd(out + hs, conn ? (ha + cprev) : ha);

        if (lane == 31 || !conn_nxt)
            atomicAdd(out + ts, c);
    } else {
        // ---- Tail path: per-lane scalar, bounds-checked, direct atomics ----
        long long base = warp_base + (long long)lane * EPT;
        if (base >= E) return;
        long long end = base + EPT < E ? base + EPT : E;
        int   cur = -1;
        float acc = 0.f;
        for (long long e = base; e < end; e++) {
            int s = seg[e];
            float val = __ldcg(cv + fi[e]);
            if (s != cur) {
                if (cur >= 0) atomicAdd(out + cur, acc);
                cur = s;
                acc = val;
            } else {
                acc += val;
            }
        }
        if (cur >= 0) atomicAdd(out + cur, acc);
    }
}

extern "C" void kernel_launch(void* const* d_in, const int* in_sizes, int n_in,
                              void* d_out, int out_size) {
    const float* cv  = (const float*)d_in[0];
    const int*   fi  = (const int*)d_in[1];
    const int*   seg = (const int*)d_in[2];
    float*       out = (float*)d_out;

    long long E = (long long)in_sizes[1];
    int N = out_size;

    // Zero output (harness poisons to 0xAA; empty segments must read 0).
    {
        int n4 = N / 4;
        int blocks = (n4 + TPB - 1) / TPB;
        zero_out_kernel<<<blocks, TPB>>>((float4*)out, n4);
    }

    long long threads_needed = (E + EPT - 1) / EPT;
    int blocks = (int)((threads_needed + TPB - 1) / TPB);
    segsum_kernel<<<blocks, TPB>>>(cv, fi, seg, out, E);
}